// round 3
// baseline (speedup 1.0000x reference)
#include <cuda_runtime.h>
#include <cstdint>

#define VOCAB 50000
#define DIM   768
#define NTOK  16384
#define BM    128
#define BN    128
#define BK    32
#define AS_STRIDE 36    // 32 + 4 pad  -> conflict-free mma-fragment LDS
#define BS_STRIDE 136   // 128 + 8 pad -> conflict-free mma-fragment LDS

__device__ int g_cnt;
__device__ int g_tok64;      // 1 if token buffer is int64, 0 if int32
__device__ int g_list[NTOK]; // token position (row in output)
__device__ int g_tok[NTOK];  // token id (row in embedding table)

// Detect token dtype from data: int64 tokens in [0,50000) have all-zero hi words.
__global__ void k_detect_reset(const int* __restrict__ words) {
    int is64 = 1;
    #pragma unroll 1
    for (int i = 1; i < 256; i += 2) {
        if (words[i] != 0) { is64 = 0; break; }
    }
    g_tok64 = is64;
    g_cnt = 0;
}

__device__ __forceinline__ int load_token(const int* __restrict__ t32, int p, int is64) {
    return is64 ? t32[2 * p] : t32[p];
}

__global__ void k_compact(const int* __restrict__ token,
                          const int* __restrict__ need) {
    int p = blockIdx.x * blockDim.x + threadIdx.x;
    if (p < NTOK) {
        int t = load_token(token, p, g_tok64);
        if (t >= 0 && t < VOCAB && need[t]) {
            int pos = atomicAdd(&g_cnt, 1);
            g_list[pos] = p;
            g_tok[pos]  = t;
        }
    }
}

// One block per token; copy embedding row for tokens that do NOT need mapping.
__global__ void k_copy(const int* __restrict__ token,
                       const int* __restrict__ need,
                       const float4* __restrict__ emb,
                       float4* __restrict__ out) {
    int p = blockIdx.x;
    int t = load_token(token, p, g_tok64);
    if (t < 0 || t >= VOCAB) return;   // defensive: never deref OOB
    if (need[t]) return;               // GEMM kernel writes these rows
    const float4* src = emb + (size_t)t * (DIM / 4);
    float4*       dst = out + (size_t)p * (DIM / 4);
    dst[threadIdx.x] = src[threadIdx.x];  // blockDim.x == 192
}

__device__ __forceinline__ uint32_t f2tf32(float x) {
    uint32_t r;
    asm("cvt.rna.tf32.f32 %0, %1;" : "=r"(r) : "f"(x));
    return r;
}

__device__ __forceinline__ void mma_tf32(float c[4], const uint32_t a[4], const uint32_t b[2]) {
    asm volatile(
        "mma.sync.aligned.m16n8k8.row.col.f32.tf32.tf32.f32 "
        "{%0,%1,%2,%3}, {%4,%5,%6,%7}, {%8,%9}, {%0,%1,%2,%3};\n"
        : "+f"(c[0]), "+f"(c[1]), "+f"(c[2]), "+f"(c[3])
        : "r"(a[0]), "r"(a[1]), "r"(a[2]), "r"(a[3]), "r"(b[0]), "r"(b[1]));
}

// GEMM over compacted needed tokens: out[list[r]] = emb[tok[r]] @ W + bias
__global__ __launch_bounds__(256, 1) void k_gemm(
    const float* __restrict__ emb, const float* __restrict__ W,
    const float* __restrict__ bias, float* __restrict__ out)
{
    const int cnt = g_cnt;
    const int mtile = blockIdx.y;
    if (mtile * BM >= cnt) return;
    const int n0 = blockIdx.x * BN;

    __shared__ uint32_t As[BM][AS_STRIDE];
    __shared__ uint32_t Bs[BK][BS_STRIDE];

    const int tid  = threadIdx.x;
    const int lane = tid & 31;
    const int wid  = tid >> 5;
    const int warp_m = (wid >> 2) * 64;   // 2 warps in M
    const int warp_n = (wid & 3) * 32;    // 4 warps in N

    // A-load mapping: 2 threads per row, 16 K-columns (4x float4) each
    const int arow  = tid >> 1;
    const int akoff = (tid & 1) * 16;
    const int gr    = mtile * BM + arow;
    const bool avalid = (gr < cnt);
    const float* arow_ptr = avalid ? (emb + (size_t)g_tok[gr] * DIM + akoff) : emb;

    // B-load mapping: thread -> k-row (tid>>3), 4x float4 across N
    const int brow  = tid >> 3;
    const int bcol  = (tid & 7) * 4;   // element offset of first float4 in N

    float acc[4][4][4];
    #pragma unroll
    for (int i = 0; i < 4; i++)
        #pragma unroll
        for (int j = 0; j < 4; j++)
            #pragma unroll
            for (int r = 0; r < 4; r++) acc[i][j][r] = 0.0f;

    float4 ar[4], br[4];

    // prologue: load chunk 0
    #pragma unroll
    for (int i = 0; i < 4; i++)
        ar[i] = avalid ? *(const float4*)(arow_ptr + i * 4)
                       : make_float4(0.f, 0.f, 0.f, 0.f);
    #pragma unroll
    for (int j = 0; j < 4; j++)
        br[j] = *(const float4*)(W + (size_t)brow * DIM + n0 + bcol + j * 32);

    const int NCHUNK = DIM / BK;  // 24
    for (int chunk = 0; chunk < NCHUNK; chunk++) {
        __syncthreads();
        // store staged regs -> smem (with RNA tf32 conversion)
        #pragma unroll
        for (int i = 0; i < 4; i++) {
            uint4 v;
            v.x = f2tf32(ar[i].x); v.y = f2tf32(ar[i].y);
            v.z = f2tf32(ar[i].z); v.w = f2tf32(ar[i].w);
            *(uint4*)&As[arow][akoff + i * 4] = v;
        }
        #pragma unroll
        for (int j = 0; j < 4; j++) {
            uint4 v;
            v.x = f2tf32(br[j].x); v.y = f2tf32(br[j].y);
            v.z = f2tf32(br[j].z); v.w = f2tf32(br[j].w);
            *(uint4*)&Bs[brow][bcol + j * 32] = v;
        }
        __syncthreads();

        // prefetch next chunk into registers (overlaps with mma below)
        if (chunk + 1 < NCHUNK) {
            const int kc = (chunk + 1) * BK;
            #pragma unroll
            for (int i = 0; i < 4; i++)
                ar[i] = avalid ? *(const float4*)(arow_ptr + kc + i * 4)
                               : make_float4(0.f, 0.f, 0.f, 0.f);
            #pragma unroll
            for (int j = 0; j < 4; j++)
                br[j] = *(const float4*)(W + (size_t)(kc + brow) * DIM + n0 + bcol + j * 32);
        }

        // compute: 4 k-steps of 8
        #pragma unroll
        for (int ks = 0; ks < 4; ks++) {
            uint32_t afr[4][4], bfr[4][2];
            const int k = ks * 8 + (lane & 3);
            #pragma unroll
            for (int fm = 0; fm < 4; fm++) {
                const int m0 = warp_m + fm * 16 + (lane >> 2);
                afr[fm][0] = As[m0][k];
                afr[fm][1] = As[m0 + 8][k];
                afr[fm][2] = As[m0][k + 4];
                afr[fm][3] = As[m0 + 8][k + 4];
            }
            #pragma unroll
            for (int fn = 0; fn < 4; fn++) {
                const int nn = warp_n + fn * 8 + (lane >> 2);
                bfr[fn][0] = Bs[k][nn];
                bfr[fn][1] = Bs[k + 4][nn];
            }
            #pragma unroll
            for (int fm = 0; fm < 4; fm++)
                #pragma unroll
                for (int fn = 0; fn < 4; fn++)
                    mma_tf32(acc[fm][fn], afr[fm], bfr[fn]);
        }
    }

    // epilogue: bias + scatter to out rows
    #pragma unroll
    for (int fm = 0; fm < 4; fm++) {
        const int r0 = mtile * BM + warp_m + fm * 16 + (lane >> 2);
        const int r1 = r0 + 8;
        #pragma unroll
        for (int fn = 0; fn < 4; fn++) {
            const int col = n0 + warp_n + fn * 8 + 2 * (lane & 3);
            const float b0 = bias[col], b1 = bias[col + 1];
            if (r0 < cnt) {
                const int p = g_list[r0];
                float2 v = make_float2(acc[fm][fn][0] + b0, acc[fm][fn][1] + b1);
                *(float2*)&out[(size_t)p * DIM + col] = v;
            }
            if (r1 < cnt) {
                const int p = g_list[r1];
                float2 v = make_float2(acc[fm][fn][2] + b0, acc[fm][fn][3] + b1);
                *(float2*)&out[(size_t)p * DIM + col] = v;
            }
        }
    }
}

extern "C" void kernel_launch(void* const* d_in, const int* in_sizes, int n_in,
                              void* d_out, int out_size) {
    const int*   token = (const int*)d_in[0];   // int32 or int64 (auto-detected)
    const int*   need  = (const int*)d_in[1];
    const float* emb   = (const float*)d_in[2];
    const float* W     = (const float*)d_in[3];
    const float* bias  = (const float*)d_in[4];
    float*       out   = (float*)d_out;

    k_detect_reset<<<1, 1>>>(token);
    k_compact<<<(NTOK + 255) / 256, 256>>>(token, need);
    k_copy<<<NTOK, DIM / 4>>>(token, need, (const float4*)emb, (float4*)out);
    k_gemm<<<dim3(DIM / BN, NTOK / BM), 256>>>(emb, W, bias, out);
}